// round 16
// baseline (speedup 1.0000x reference)
#include <cuda_runtime.h>
#include <stdint.h>

#define NSIDE 48
#define PITCH 52                 // padded row stride (floats); 16B-aligned rows
#define NPIX  (NSIDE*NSIDE)      // 2304
#define MAT   (NSIDE*PITCH)      // 2496
#define CSIZE 4                  // CTAs per cluster (per batch)
#define RPC   (NSIDE/CSIZE)      // 12 rows owned per CTA
#define NTHR  192
#define NWARP (NTHR/32)

typedef unsigned long long u64;

__device__ __forceinline__ uint32_t smem_u32(const void* p) {
    return (uint32_t)__cvta_generic_to_shared(p);
}

__device__ __forceinline__ void st_remote(uint32_t laddr, uint32_t rank, float v) {
    uint32_t raddr;
    asm volatile("mapa.shared::cluster.u32 %0, %1, %2;"
                 : "=r"(raddr) : "r"(laddr), "r"(rank));
    asm volatile("st.shared::cluster.b32 [%0], %1;"
                 :: "r"(raddr), "r"(__float_as_uint(v)) : "memory");
}

#define CLUSTER_ARRIVE() asm volatile("barrier.cluster.arrive.aligned;" ::: "memory")
#define CLUSTER_WAIT()   asm volatile("barrier.cluster.wait.aligned;"   ::: "memory")

__device__ __forceinline__ void cluster_sync_() {
    CLUSTER_ARRIVE();
    CLUSTER_WAIT();
}

// packed 2-wide fp32 FMA (sm_100+): d = a*b + c elementwise on float pairs
__device__ __forceinline__ u64 fma2(u64 a, u64 b, u64 c) {
    u64 d;
    asm("fma.rn.f32x2 %0, %1, %2, %3;" : "=l"(d) : "l"(a), "l"(b), "l"(c));
    return d;
}

// horizontal sum of a packed pair
__device__ __forceinline__ float hsum2(u64 v) {
    uint32_t lo, hi;
    asm("mov.b64 {%0, %1}, %2;" : "=r"(lo), "=r"(hi) : "l"(v));
    return __uint_as_float(lo) + __uint_as_float(hi);
}

// Block-wide sum (192 threads = 6 warps)
__device__ __forceinline__ float block_sum(float v, float* red) {
    const int lane = threadIdx.x & 31;
    const int wid  = threadIdx.x >> 5;
    #pragma unroll
    for (int o = 16; o > 0; o >>= 1) v += __shfl_xor_sync(0xffffffffu, v, o);
    if (lane == 0) red[wid] = v;
    __syncthreads();
    if (wid == 0) {
        float x = (lane < NWARP) ? red[lane] : 0.0f;
        #pragma unroll
        for (int o = 4; o > 0; o >>= 1) x += __shfl_xor_sync(0xffffffffu, x, o);
        if (lane == 0) red[0] = x;
    }
    __syncthreads();
    float r = red[0];
    __syncthreads();
    return r;
}

// 12-k chunk, packed: acc2[0..2] += a[k..k+12) . b{0,1,2}[k..k+12)
// Operands loaded as ulonglong2 (one LDS.128 = 2 packed f32 pairs).
__device__ __forceinline__ void mmk12(const float* __restrict__ a,
                                      const float* __restrict__ b0,
                                      u64 acc[3]) {
    const float* b1 = b0 + PITCH;
    const float* b2 = b0 + 2*PITCH;
    #pragma unroll
    for (int q = 0; q < 3; q++) {
        ulonglong2 av = *(const ulonglong2*)(a  + 4*q);
        ulonglong2 B0 = *(const ulonglong2*)(b0 + 4*q);
        ulonglong2 B1 = *(const ulonglong2*)(b1 + 4*q);
        ulonglong2 B2 = *(const ulonglong2*)(b2 + 4*q);
        acc[0] = fma2(av.x, B0.x, acc[0]); acc[0] = fma2(av.y, B0.y, acc[0]);
        acc[1] = fma2(av.x, B1.x, acc[1]); acc[1] = fma2(av.y, B1.y, acc[1]);
        acc[2] = fma2(av.x, B2.x, acc[2]); acc[2] = fma2(av.y, B2.y, acc[2]);
    }
}

// dual-A 12-k chunk, packed (B loaded once)
__device__ __forceinline__ void mmk12_dual(const float* __restrict__ a1,
                                           const float* __restrict__ a2,
                                           const float* __restrict__ b0,
                                           u64 acc_a[3], u64 acc_b[3]) {
    const float* b1 = b0 + PITCH;
    const float* b2 = b0 + 2*PITCH;
    #pragma unroll
    for (int q = 0; q < 3; q++) {
        ulonglong2 a1v = *(const ulonglong2*)(a1 + 4*q);
        ulonglong2 a2v = *(const ulonglong2*)(a2 + 4*q);
        ulonglong2 B0 = *(const ulonglong2*)(b0 + 4*q);
        ulonglong2 B1 = *(const ulonglong2*)(b1 + 4*q);
        ulonglong2 B2 = *(const ulonglong2*)(b2 + 4*q);
        acc_a[0] = fma2(a1v.x, B0.x, acc_a[0]); acc_a[0] = fma2(a1v.y, B0.y, acc_a[0]);
        acc_a[1] = fma2(a1v.x, B1.x, acc_a[1]); acc_a[1] = fma2(a1v.y, B1.y, acc_a[1]);
        acc_a[2] = fma2(a1v.x, B2.x, acc_a[2]); acc_a[2] = fma2(a1v.y, B2.y, acc_a[2]);
        acc_b[0] = fma2(a2v.x, B0.x, acc_b[0]); acc_b[0] = fma2(a2v.y, B0.y, acc_b[0]);
        acc_b[1] = fma2(a2v.x, B1.x, acc_b[1]); acc_b[1] = fma2(a2v.y, B1.y, acc_b[1]);
        acc_b[2] = fma2(a2v.x, B2.x, acc_b[2]); acc_b[2] = fma2(a2v.y, B2.y, acc_b[2]);
    }
}

// full 48-k contraction, packed
__device__ __forceinline__ void mm1x3(const float* __restrict__ a,
                                      const float* __restrict__ b0,
                                      u64 acc[3]) {
    #pragma unroll
    for (int k0 = 0; k0 < NSIDE; k0 += 12) mmk12(a + k0, b0 + k0, acc);
}

#define ZP3(a) do { (a)[0]=0ull; (a)[1]=0ull; (a)[2]=0ull; } while(0)

__global__ void __launch_bounds__(NTHR, 1) __cluster_dims__(CSIZE, 1, 1)
sinkhorn_kernel(const float* __restrict__ img_pred,
                const float* __restrict__ img_target,
                const float* __restrict__ cm,
                float* __restrict__ out)
{
    __shared__ float G[MAT];        // exp(-c1d/eps), symmetric
    __shared__ float G2[MAT];       // G * c1d, symmetric
    __shared__ float At[MAT];       // transpose of exp(alpha) image (replicated)
    __shared__ float Bt[MAT];       // transpose of exp(beta) image  (replicated)
    __shared__ float U[RPC*PITCH];  // stage-1 result (primary)
    __shared__ float U1[RPC*PITCH]; // stage-1 result (secondary, fused tail)
    __shared__ float srow[NSIDE];   // row sums of G (peeled first step)
    __shared__ float red[24];

    const int tid   = threadIdx.x;
    const int rank  = blockIdx.x & (CSIZE-1);
    const int batch = blockIdx.x / CSIZE;
    const int s1row = tid >> 4;             // 0..11 local output row
    const int j0    = 3 * (tid & 15);       // output col group
    const int ig    = rank * RPC + s1row;   // global output row
    const int kown  = rank * RPC;           // this CTA's own k-chunk base

    // ---- build G, G2 from the cost_matrix input (coalesced top-left block) ----
    // cm[a*2304 + b] = cost((0,a),(0,b)) = ((a-b)/48)^2 — the separable 1-D term
    for (int idx = tid; idx < NPIX; idx += NTHR) {
        int r = idx / NSIDE, c = idx - r * NSIDE;
        float cy = cm[(size_t)r * NPIX + c];
        float g  = __expf(-100.0f * cy);     // exp(-c/EPS), EPS=0.01
        G [r*PITCH + c] = g;
        G2[r*PITCH + c] = g * cy;
    }

    // ---- normalized marginals (channel 0) ----
    const float* p = img_pred   + (size_t)batch * 3 * NPIX;
    const float* t = img_target + (size_t)batch * 3 * NPIX;
    float sp = 0.0f, st = 0.0f;
    for (int i = tid; i < NPIX; i += NTHR) { sp += p[i]; st += t[i]; }
    sp = block_sum(sp, red) + NPIX * 1e-9f;   // block_sum syncs; G now visible
    st = block_sum(st, red) + NPIX * 1e-9f;
    const float isp = 1.0f / sp, ist = 1.0f / st;

    // row sums of G for the peeled first u half-step (EB = 1)
    if (tid < NSIDE) {
        float s = 0.0f;
        #pragma unroll
        for (int q = 0; q < 12; q++) {
            float4 v = *(const float4*)(G + tid*PITCH + 4*q);
            s += (v.x + v.y) + (v.z + v.w);
        }
        srow[tid] = s;
    }

    // this thread's pixels: (ig, j0..j0+2). Scaling form of Sinkhorn:
    //   ea' = eu*ea / (ea*T + 1e-6)
    float eu[3], ev[3], ea[3], eb[3];
    #pragma unroll
    for (int c = 0; c < 3; c++) {
        int pix = ig * NSIDE + j0 + c;
        eu[c] = (p[pix] + 1e-9f) * isp;
        ev[c] = (t[pix] + 1e-9f) * ist;
        ea[c] = 1.0f;
        eb[c] = 1.0f;
    }
    __syncthreads();

    const float* Ga  = G  + ig*PITCH;        // stage-1 A row (G)
    const float* G2a = G2 + ig*PITCH;        // stage-1 A row (G2)
    const float* Gb  = G  + j0*PITCH;        // stage-2 B rows (G)
    const float* G2b = G2 + j0*PITCH;        // stage-2 B rows (G2)
    const float* Ur  = U  + s1row*PITCH;     // stage-2 A row
    const float* U1r = U1 + s1row*PITCH;
    float* Uw  = U  + s1row*PITCH + j0;
    float* U1w = U1 + s1row*PITCH + j0;

    u64 acc[3], accp[3], accp1[3];

    // Overlap scheme (as R14): ARRIVE -> __syncthreads -> own-k chunk of the
    // next stage-1 (reads only locally-produced columns; peer DSMEM stores
    // land in disjoint columns) -> WAIT -> peer k-chunks.

    // ======== peeled first u half-step: T = G*1*G = srow_i * srow_j ========
    {
        float si = srow[ig];
        #pragma unroll
        for (int c = 0; c < 3; c++) {
            float e = __fdividef(eu[c], fmaf(si, srow[j0 + c], 1e-6f));
            ea[c] = e;
            int off = (j0 + c) * PITCH + ig;      // transposed store
            At[off] = e;
            uint32_t la = smem_u32(&At[off]);
            #pragma unroll
            for (int rr = 1; rr < CSIZE; rr++)
                st_remote(la, (uint32_t)((rank + rr) & (CSIZE-1)), e);
        }
        CLUSTER_ARRIVE();
        __syncthreads();
        ZP3(accp);
        mmk12(Ga + kown, At + j0*PITCH + kown, accp);   // own-k of v stage-1
        CLUSTER_WAIT();
    }

    // 4 full (v,u) pairs; the 5th v is fused with the cost phase below.
    #pragma unroll 1
    for (int it = 0; it < 4; it++) {
        // ======== v half-step: T = G * EA * G (K symmetric) ========
        acc[0]=accp[0]; acc[1]=accp[1]; acc[2]=accp[2];
        #pragma unroll
        for (int cc = 1; cc < CSIZE; cc++) {           // 3 peer k-chunks
            int k0 = ((rank + cc) & (CSIZE-1)) * RPC;
            mmk12(Ga + k0, At + j0*PITCH + k0, acc);
        }
        Uw[0]=hsum2(acc[0]); Uw[1]=hsum2(acc[1]); Uw[2]=hsum2(acc[2]);
        __syncwarp();

        ZP3(acc);
        mm1x3(Ur, Gb, acc);                            // T = U * G
        #pragma unroll
        for (int c = 0; c < 3; c++) {
            float tc = hsum2(acc[c]);
            float e = __fdividef(ev[c] * eb[c], fmaf(eb[c], tc, 1e-6f));
            eb[c] = e;
            int off = (j0 + c) * PITCH + ig;
            Bt[off] = e;
            uint32_t la = smem_u32(&Bt[off]);
            #pragma unroll
            for (int rr = 1; rr < CSIZE; rr++)
                st_remote(la, (uint32_t)((rank + rr) & (CSIZE-1)), e);
        }
        __syncwarp();
        CLUSTER_ARRIVE();
        __syncthreads();
        ZP3(accp);
        mmk12(Ga + kown, Bt + j0*PITCH + kown, accp);  // own-k of u stage-1
        CLUSTER_WAIT();

        // ======== u half-step: T = G * EB * G ========
        acc[0]=accp[0]; acc[1]=accp[1]; acc[2]=accp[2];
        #pragma unroll
        for (int cc = 1; cc < CSIZE; cc++) {
            int k0 = ((rank + cc) & (CSIZE-1)) * RPC;
            mmk12(Ga + k0, Bt + j0*PITCH + k0, acc);
        }
        Uw[0]=hsum2(acc[0]); Uw[1]=hsum2(acc[1]); Uw[2]=hsum2(acc[2]);
        __syncwarp();

        ZP3(acc);
        mm1x3(Ur, Gb, acc);                            // T = U * G
        #pragma unroll
        for (int c = 0; c < 3; c++) {
            float tc = hsum2(acc[c]);
            float e = __fdividef(eu[c] * ea[c], fmaf(ea[c], tc, 1e-6f));
            ea[c] = e;
            int off = (j0 + c) * PITCH + ig;
            At[off] = e;
            uint32_t la = smem_u32(&At[off]);
            #pragma unroll
            for (int rr = 1; rr < CSIZE; rr++)
                st_remote(la, (uint32_t)((rank + rr) & (CSIZE-1)), e);
        }
        __syncwarp();
        CLUSTER_ARRIVE();
        __syncthreads();
        ZP3(accp);
        if (it < 3) {
            mmk12(Ga + kown, At + j0*PITCH + kown, accp);   // own-k of next v
        } else {
            ZP3(accp1);                                     // own-k of fused tail
            mmk12_dual(Ga + kown, G2a + kown, At + j0*PITCH + kown, accp, accp1);
        }
        CLUSTER_WAIT();
    }

    // ======== fused: 5th v half-step + cost ========
    // cost = sum EA.*(G2 EB G + G EB G2) == sum EB.*(G2 EA G + G EA G2)
    // (G, G2 symmetric). eb is in registers; At already mirrored. No Bt
    // mirror, no extra cluster sync.
    float csum = 0.0f;
    {
        #pragma unroll
        for (int cc = 1; cc < CSIZE; cc++) {
            int k0 = ((rank + cc) & (CSIZE-1)) * RPC;
            mmk12_dual(Ga + k0, G2a + k0, At + j0*PITCH + k0, accp, accp1);
        }
        Uw[0]=hsum2(accp[0]);  Uw[1]=hsum2(accp[1]);  Uw[2]=hsum2(accp[2]);   // U  = G  * EA
        U1w[0]=hsum2(accp1[0]); U1w[1]=hsum2(accp1[1]); U1w[2]=hsum2(accp1[2]); // U1 = G2 * EA
        __syncwarp();

        // T = (G*EA)*G  -> eb update (local only)
        ZP3(acc);
        mm1x3(Ur, Gb, acc);
        #pragma unroll
        for (int c = 0; c < 3; c++) {
            float tc = hsum2(acc[c]);
            eb[c] = __fdividef(ev[c] * eb[c], fmaf(eb[c], tc, 1e-6f));
        }

        // Tf = (G*EA)*G2 + (G2*EA)*G  -> cost contraction with eb
        u64 accf[3]; ZP3(accf);
        mm1x3(Ur,  G2b, accf);
        mm1x3(U1r, Gb,  accf);
        #pragma unroll
        for (int c = 0; c < 3; c++) csum += eb[c] * hsum2(accf[c]);
    }

    csum = block_sum(csum, red);

    // cluster reduction into rank 0
    if (tid == 0) {
        if (rank == 0) red[16] = csum;
        else st_remote(smem_u32(&red[16 + rank]), 0u, csum);
    }
    cluster_sync_();
    if (rank == 0 && tid == 0)
        out[batch] = red[16] + red[17] + red[18] + red[19];
}

extern "C" void kernel_launch(void* const* d_in, const int* in_sizes, int n_in,
                              void* d_out, int out_size) {
    const float* img_pred   = (const float*)d_in[0];
    const float* img_target = (const float*)d_in[1];
    const float* cm         = (const float*)d_in[2];
    float* out = (float*)d_out;

    const int B = in_sizes[0] / (3 * NPIX);   // 32
    sinkhorn_kernel<<<B * CSIZE, NTHR>>>(img_pred, img_target, cm, out);
}